// round 4
// baseline (speedup 1.0000x reference)
#include <cuda_runtime.h>
#include <cuda_bf16.h>
#include <cstdint>

#define NN   100000
#define EE   1600000
#define FIN  256
#define HID  128
#define NC   16

// ---------------- scratch ----------------------------------------------------
static __device__ float g_h[(size_t)NN * HID];     // h' = (x@W1) * dinv[row]
static __device__ float g_agg1[(size_t)NN * HID];  // init h'[i], += h'[src]
static __device__ float g_z[(size_t)NN * NC];      // z' = (relu(...)@W2)*dinv
static __device__ float g_dinv[NN];
static __device__ int   g_deg[NN];

// ---------------- degree / normalization ------------------------------------
__global__ void k_deg_init() {
    int i = blockIdx.x * blockDim.x + threadIdx.x;
    if (i < NN) g_deg[i] = 1;   // self loop
}
__global__ void k_deg_count(const int* __restrict__ dst) {
    int e = blockIdx.x * blockDim.x + threadIdx.x;
    if (e < EE) atomicAdd(&g_deg[dst[e]], 1);
}
__global__ void k_dinv() {
    int i = blockIdx.x * blockDim.x + threadIdx.x;
    if (i < NN) g_dinv[i] = rsqrtf((float)g_deg[i]);
}

// ---------------- bf16 split helpers -----------------------------------------
// pack two f32 (k0 -> low half, k1 -> high half) into bf16x2
__device__ __forceinline__ uint32_t pack_bf16x2(float k1, float k0) {
    uint32_t r;
    asm("cvt.rn.bf16x2.f32 %0, %1, %2;" : "=r"(r) : "f"(k1), "f"(k0));
    return r;
}
// exact f32 value of the low / high bf16 halves
__device__ __forceinline__ float bf_lo(uint32_t u) { return __uint_as_float(u << 16); }
__device__ __forceinline__ float bf_hi(uint32_t u) { return __uint_as_float(u & 0xFFFF0000u); }

__device__ __forceinline__ void mma_bf16(float* d, const uint32_t* a, const uint32_t* b) {
    asm volatile(
        "mma.sync.aligned.m16n8k16.row.col.f32.bf16.bf16.f32 "
        "{%0,%1,%2,%3}, {%4,%5,%6,%7}, {%8,%9}, {%0,%1,%2,%3};"
        : "+f"(d[0]), "+f"(d[1]), "+f"(d[2]), "+f"(d[3])
        : "r"(a[0]), "r"(a[1]), "r"(a[2]), "r"(a[3]), "r"(b[0]), "r"(b[1]));
}

// ---------------- GEMM1: g_h = (x[N,256] @ W1[256,128]) * dinv ---------------
// 128x128 block tile, BK=16, 256 threads (8 warps: 2Mx4N, warp tile 64x32).
// 3xBF16 split (ah*bh + al*bh + ah*bl), split done ONCE at smem staging.
// Smem holds k-pair-packed bf16x2 matching the m16n8k16 fragment layout.
__global__ __launch_bounds__(256) void k_gemm1(const float* __restrict__ A,
                                               const float* __restrict__ B) {
    __shared__ uint32_t As_h[2][128][8];   // [buf][row][kpair]
    __shared__ uint32_t As_l[2][128][8];
    __shared__ uint32_t Bs_h[2][128][8];   // [buf][col][kpair]
    __shared__ uint32_t Bs_l[2][128][8];

    const int tid  = threadIdx.x;
    const int warp = tid >> 5, lane = tid & 31;
    const int blockM = blockIdx.x * 128;
    const int wm = (warp >> 2) * 64;   // 0 / 64
    const int wn = (warp & 3) * 32;    // 0..96

    float acc[4][4][4];
    #pragma unroll
    for (int i = 0; i < 4; i++)
        #pragma unroll
        for (int j = 0; j < 4; j++)
            #pragma unroll
            for (int q = 0; q < 4; q++) acc[i][j][q] = 0.f;

    // staging registers (double buffer)
    float4 av[2];         // A: 2 float4 per thread
    float4 bv0, bv1;      // B: kpair rows

    const int aR  = tid >> 2;            // row for i=0 (rows 0..63); i=1 adds 64
    const int aKq = (tid & 3) * 4;       // k offset 0,4,8,12
    const int bP  = tid >> 5;            // kpair 0..7
    const int bC  = (tid & 31) * 4;      // col group

    auto loadChunk = [&](int k0) {
        #pragma unroll
        for (int i = 0; i < 2; i++) {
            int gr = blockM + aR + 64 * i;
            av[i] = (gr < NN) ? *(const float4*)&A[(size_t)gr * FIN + k0 + aKq]
                              : make_float4(0.f, 0.f, 0.f, 0.f);
        }
        bv0 = *(const float4*)&B[(size_t)(k0 + 2 * bP)     * HID + bC];
        bv1 = *(const float4*)&B[(size_t)(k0 + 2 * bP + 1) * HID + bC];
    };
    auto storeChunk = [&](int buf) {
        #pragma unroll
        for (int i = 0; i < 2; i++) {
            int r = aR + 64 * i;
            uint32_t h0 = pack_bf16x2(av[i].y, av[i].x);
            uint32_t h1 = pack_bf16x2(av[i].w, av[i].z);
            uint32_t l0 = pack_bf16x2(av[i].y - bf_hi(h0), av[i].x - bf_lo(h0));
            uint32_t l1 = pack_bf16x2(av[i].w - bf_hi(h1), av[i].z - bf_lo(h1));
            *(uint2*)&As_h[buf][r][aKq >> 1] = make_uint2(h0, h1);
            *(uint2*)&As_l[buf][r][aKq >> 1] = make_uint2(l0, l1);
        }
        // B: pack (k=2p, k=2p+1) pairs for 4 consecutive cols
        float bk0[4] = {bv0.x, bv0.y, bv0.z, bv0.w};
        float bk1[4] = {bv1.x, bv1.y, bv1.z, bv1.w};
        #pragma unroll
        for (int j = 0; j < 4; j++) {
            uint32_t h = pack_bf16x2(bk1[j], bk0[j]);
            uint32_t l = pack_bf16x2(bk1[j] - bf_hi(h), bk0[j] - bf_lo(h));
            Bs_h[buf][bC + j][bP] = h;
            Bs_l[buf][bC + j][bP] = l;
        }
    };

    loadChunk(0);
    storeChunk(0);
    __syncthreads();

    const int fr  = lane >> 2;      // fragment row/col offset
    const int fkp = lane & 3;       // fragment kpair

    for (int ch = 0; ch < 16; ch++) {
        const int buf = ch & 1;
        if (ch < 15) loadChunk((ch + 1) * 16);

        uint32_t ah[4][4], bh[4][2];
        #pragma unroll
        for (int mt = 0; mt < 4; mt++) {
            int r = wm + mt * 16 + fr;
            ah[mt][0] = As_h[buf][r][fkp];
            ah[mt][1] = As_h[buf][r + 8][fkp];
            ah[mt][2] = As_h[buf][r][fkp + 4];
            ah[mt][3] = As_h[buf][r + 8][fkp + 4];
        }
        #pragma unroll
        for (int nt = 0; nt < 4; nt++) {
            int c = wn + nt * 8 + fr;
            bh[nt][0] = Bs_h[buf][c][fkp];
            bh[nt][1] = Bs_h[buf][c][fkp + 4];
        }
        #pragma unroll
        for (int mt = 0; mt < 4; mt++)
            #pragma unroll
            for (int nt = 0; nt < 4; nt++)
                mma_bf16(acc[mt][nt], ah[mt], bh[nt]);

        {   // al * bh
            uint32_t al[4][4];
            #pragma unroll
            for (int mt = 0; mt < 4; mt++) {
                int r = wm + mt * 16 + fr;
                al[mt][0] = As_l[buf][r][fkp];
                al[mt][1] = As_l[buf][r + 8][fkp];
                al[mt][2] = As_l[buf][r][fkp + 4];
                al[mt][3] = As_l[buf][r + 8][fkp + 4];
            }
            #pragma unroll
            for (int mt = 0; mt < 4; mt++)
                #pragma unroll
                for (int nt = 0; nt < 4; nt++)
                    mma_bf16(acc[mt][nt], al[mt], bh[nt]);
        }
        {   // ah * bl
            uint32_t bl[4][2];
            #pragma unroll
            for (int nt = 0; nt < 4; nt++) {
                int c = wn + nt * 8 + fr;
                bl[nt][0] = Bs_l[buf][c][fkp];
                bl[nt][1] = Bs_l[buf][c][fkp + 4];
            }
            #pragma unroll
            for (int mt = 0; mt < 4; mt++)
                #pragma unroll
                for (int nt = 0; nt < 4; nt++)
                    mma_bf16(acc[mt][nt], ah[mt], bl[nt]);
        }

        if (ch < 15) storeChunk(buf ^ 1);
        __syncthreads();
    }

    // epilogue: scale by dinv[row], write to g_h AND g_agg1 (self-loop init)
    #pragma unroll
    for (int mt = 0; mt < 4; mt++) {
        #pragma unroll
        for (int half = 0; half < 2; half++) {
            int r = blockM + wm + mt * 16 + (lane >> 2) + half * 8;
            if (r < NN) {
                float di = g_dinv[r];
                #pragma unroll
                for (int nt = 0; nt < 4; nt++) {
                    int c = wn + nt * 8 + 2 * (lane & 3);
                    float2 v = make_float2(acc[mt][nt][half * 2 + 0] * di,
                                           acc[mt][nt][half * 2 + 1] * di);
                    *(float2*)&g_h[(size_t)r * HID + c]    = v;
                    *(float2*)&g_agg1[(size_t)r * HID + c] = v;
                }
            }
        }
    }
}

// ---------------- aggregate layer 1: warp per edge, red.v4 ------------------
__global__ __launch_bounds__(256) void k_agg1(const int* __restrict__ src,
                                              const int* __restrict__ dst) {
    int w = (blockIdx.x * blockDim.x + threadIdx.x) >> 5;
    int lane = threadIdx.x & 31;
    if (w >= EE) return;
    int s = __ldg(&src[w]);
    int d = __ldg(&dst[w]);
    float4 v = *(const float4*)&g_h[(size_t)s * HID + lane * 4];
    float* p = &g_agg1[(size_t)d * HID + lane * 4];
    asm volatile("red.global.add.v4.f32 [%0], {%1,%2,%3,%4};"
                 :: "l"(p), "f"(v.x), "f"(v.y), "f"(v.z), "f"(v.w)
                 : "memory");
}

// ---------------- GEMM2: z' = (relu(dinv*agg1 + b1) @ W2) * dinv ------------
__global__ __launch_bounds__(256) void k_gemm2(const float* __restrict__ b1,
                                               const float* __restrict__ W2,
                                               float* __restrict__ out) {
    __shared__ float sRow[16][132];
    __shared__ float sW[HID * NC];
    __shared__ float sB1[HID];
    __shared__ float sDi[16];
    const int tid = threadIdx.x;
    const int nb = blockIdx.x * 16;

    #pragma unroll
    for (int i = 0; i < 2; i++) {
        int idx = tid + 256 * i;
        int r = idx >> 5, c = (idx & 31) * 4;
        int node = nb + r;
        float4 v = (node < NN) ? *(const float4*)&g_agg1[(size_t)node * HID + c]
                               : make_float4(0.f, 0.f, 0.f, 0.f);
        *(float4*)&sRow[r][c] = v;
    }
    for (int i = tid; i < HID * NC; i += 256) sW[i] = W2[i];
    if (tid < HID) sB1[tid] = b1[tid];
    if (tid < 16) { int node = nb + tid; sDi[tid] = (node < NN) ? g_dinv[node] : 0.f; }
    __syncthreads();

    int ln = tid >> 4, c = tid & 15;
    int node = nb + ln;
    if (node >= NN) return;
    float di = sDi[ln];
    float acc = 0.f;
    #pragma unroll
    for (int k = 0; k < HID; k++) {
        float a = fmaf(sRow[ln][k], di, sB1[k]);
        a = fmaxf(a, 0.f);
        acc = fmaf(a, sW[k * NC + c], acc);
    }
    float zp = acc * di;
    g_z[(size_t)node * NC + c] = zp;   // gather source
    out[(size_t)node * NC + c] = zp;   // self-loop init of accumulator
}

// ---------------- aggregate layer 2: 4 threads per edge, red.v4 -------------
__global__ __launch_bounds__(256) void k_agg2(const int* __restrict__ src,
                                              const int* __restrict__ dst,
                                              float* __restrict__ out) {
    int gid = blockIdx.x * blockDim.x + threadIdx.x;
    int e = gid >> 2;
    if (e >= EE) return;
    int q = gid & 3;
    int s = __ldg(&src[e]);
    int d = __ldg(&dst[e]);
    float4 v = *(const float4*)&g_z[(size_t)s * NC + q * 4];
    float* p = &out[(size_t)d * NC + q * 4];
    asm volatile("red.global.add.v4.f32 [%0], {%1,%2,%3,%4};"
                 :: "l"(p), "f"(v.x), "f"(v.y), "f"(v.z), "f"(v.w)
                 : "memory");
}

// ---------------- final scale + bias -----------------------------------------
__global__ void k_final(const float* __restrict__ b2, float* __restrict__ out) {
    int i = blockIdx.x * blockDim.x + threadIdx.x;
    if (i < NN * NC) out[i] = fmaf(out[i], g_dinv[i >> 4], b2[i & (NC - 1)]);
}

// ---------------- launch -----------------------------------------------------
extern "C" void kernel_launch(void* const* d_in, const int* in_sizes, int n_in,
                              void* d_out, int out_size) {
    const float* x  = (const float*)d_in[0];
    const int*   ei = (const int*)d_in[1];
    const float* W1 = (const float*)d_in[2];
    const float* b1 = (const float*)d_in[3];
    const float* W2 = (const float*)d_in[4];
    const float* b2 = (const float*)d_in[5];
    float* out = (float*)d_out;

    const int* src = ei;        // edge_index[0]
    const int* dst = ei + EE;   // edge_index[1]

    k_deg_init<<<(NN + 255) / 256, 256>>>();
    k_deg_count<<<(EE + 255) / 256, 256>>>(dst);
    k_dinv<<<(NN + 255) / 256, 256>>>();

    k_gemm1<<<(NN + 127) / 128, 256>>>(x, W1);      // h' + agg1 init

    k_agg1<<<EE / 8, 256>>>(src, dst);              // warp per edge

    k_gemm2<<<(NN + 15) / 16, 256>>>(b1, W2, out);  // z' + out init

    k_agg2<<<(EE * 4 + 255) / 256, 256>>>(src, dst, out);

    k_final<<<(NN * NC + 255) / 256, 256>>>(b2, out);
}

// round 5
// speedup vs baseline: 1.5044x; 1.5044x over previous
#include <cuda_runtime.h>
#include <cuda_bf16.h>
#include <cstdint>

#define NN   100000
#define EE   1600000
#define FIN  256
#define HID  128
#define NC   16
#define NB_SCAN ((NN + 1023) / 1024)

// ---------------- scratch ----------------------------------------------------
static __device__ float g_h[(size_t)NN * HID];     // h' = (x@W1) * dinv[row]
static __device__ float g_z[(size_t)NN * NC];      // z' = (relu(...)@W2)*dinv
static __device__ float g_dinv[NN];
static __device__ int   g_deg[NN];
static __device__ int   g_rowptr[NN + 1];
static __device__ int   g_cursor[NN];
static __device__ int   g_adj[EE];                 // src ids grouped by dst
static __device__ int   g_bsum[NB_SCAN];

// ---------------- degree / normalization ------------------------------------
__global__ void k_deg_init() {
    int i = blockIdx.x * blockDim.x + threadIdx.x;
    if (i < NN) g_deg[i] = 1;   // self loop
}
__global__ void k_deg_count(const int* __restrict__ dst) {
    int e = blockIdx.x * blockDim.x + threadIdx.x;
    if (e < EE) atomicAdd(&g_deg[dst[e]], 1);
}
__global__ void k_dinv() {
    int i = blockIdx.x * blockDim.x + threadIdx.x;
    if (i < NN) g_dinv[i] = rsqrtf((float)g_deg[i]);
}

// ---------------- CSR build: scan of (deg-1), then scatter fill --------------
__global__ __launch_bounds__(256) void k_scan_block() {
    __shared__ int sS[256];
    const int t = threadIdx.x;
    const int base = blockIdx.x * 1024 + t * 4;
    int v[4], s = 0;
    #pragma unroll
    for (int q = 0; q < 4; q++) {
        int i = base + q;
        v[q] = (i < NN) ? (g_deg[i] - 1) : 0;
        s += v[q];
    }
    sS[t] = s;
    __syncthreads();
    #pragma unroll
    for (int off = 1; off < 256; off <<= 1) {
        int x = (t >= off) ? sS[t - off] : 0;
        __syncthreads();
        sS[t] += x;
        __syncthreads();
    }
    if (t == 255) g_bsum[blockIdx.x] = sS[255];
    int run = sS[t] - s;   // exclusive prefix within block
    #pragma unroll
    for (int q = 0; q < 4; q++) {
        int i = base + q;
        if (i < NN) g_rowptr[i] = run;
        run += v[q];
    }
}
__global__ void k_scan_top() {
    int run = 0;
    for (int b = 0; b < NB_SCAN; b++) { int t = g_bsum[b]; g_bsum[b] = run; run += t; }
}
__global__ void k_scan_add() {
    int i = blockIdx.x * blockDim.x + threadIdx.x;
    if (i < NN) {
        int r = g_rowptr[i] + g_bsum[i >> 10];
        g_rowptr[i] = r;
        g_cursor[i] = r;
    }
    if (i == 0) g_rowptr[NN] = EE;
}
__global__ void k_fill(const int* __restrict__ src, const int* __restrict__ dst) {
    int e = blockIdx.x * blockDim.x + threadIdx.x;
    if (e < EE) {
        int d = dst[e];
        int pos = atomicAdd(&g_cursor[d], 1);
        g_adj[pos] = src[e];
    }
}

// ---------------- tf32 helpers -----------------------------------------------
__device__ __forceinline__ float tf32_rna(float v) {
    uint32_t u;
    asm("cvt.rna.tf32.f32 %0, %1;" : "=r"(u) : "f"(v));
    return __uint_as_float(u);
}
__device__ __forceinline__ void mma_tf32(float* d, const uint32_t* a, const uint32_t* b) {
    asm volatile(
        "mma.sync.aligned.m16n8k8.row.col.f32.tf32.tf32.f32 "
        "{%0,%1,%2,%3}, {%4,%5,%6,%7}, {%8,%9}, {%0,%1,%2,%3};"
        : "+f"(d[0]), "+f"(d[1]), "+f"(d[2]), "+f"(d[3])
        : "r"(a[0]), "r"(a[1]), "r"(a[2]), "r"(a[3]), "r"(b[0]), "r"(b[1]));
}

// ---------------- GEMM1: g_h = (x[N,256] @ W1[256,128]) * dinv ---------------
// (round-2 kernel: 128x128 tile, BK=16, 8 warps, 3xTF32 split)
__global__ __launch_bounds__(256) void k_gemm1(const float* __restrict__ A,
                                               const float* __restrict__ B) {
    __shared__ float As[2][128][20];
    __shared__ float Bs[2][16][132];

    const int tid  = threadIdx.x;
    const int warp = tid >> 5, lane = tid & 31;
    const int blockM = blockIdx.x * 128;
    const int wm = (warp >> 2) * 64;
    const int wn = (warp & 3) * 32;

    float acc[4][4][4];
    #pragma unroll
    for (int i = 0; i < 4; i++)
        #pragma unroll
        for (int j = 0; j < 4; j++)
            #pragma unroll
            for (int q = 0; q < 4; q++) acc[i][j][q] = 0.f;

    float4 aReg[2], bReg[2];

    auto loadChunk = [&](int k0) {
        #pragma unroll
        for (int i = 0; i < 2; i++) {
            int idx = tid + 256 * i;
            int r = idx >> 2, c = (idx & 3) * 4;
            int gr = blockM + r;
            aReg[i] = (gr < NN) ? *(const float4*)&A[(size_t)gr * FIN + k0 + c]
                                : make_float4(0.f, 0.f, 0.f, 0.f);
            int bk = idx >> 5, bc = (idx & 31) * 4;
            bReg[i] = *(const float4*)&B[(size_t)(k0 + bk) * HID + bc];
        }
    };
    auto storeChunk = [&](int buf) {
        #pragma unroll
        for (int i = 0; i < 2; i++) {
            int idx = tid + 256 * i;
            int r = idx >> 2, c = (idx & 3) * 4;
            *(float4*)&As[buf][r][c] = aReg[i];
            int bk = idx >> 5, bc = (idx & 31) * 4;
            *(float4*)&Bs[buf][bk][bc] = bReg[i];
        }
    };

    loadChunk(0);
    storeChunk(0);
    __syncthreads();

    for (int ch = 0; ch < 16; ch++) {
        const int buf = ch & 1;
        if (ch < 15) loadChunk((ch + 1) * 16);

        #pragma unroll
        for (int ks = 0; ks < 2; ks++) {
            const int kk = ks * 8;
            uint32_t ah[4][4], al[4][4];
            #pragma unroll
            for (int mt = 0; mt < 4; mt++) {
                int r = wm + mt * 16 + (lane >> 2);
                int c = kk + (lane & 3);
                float v0 = As[buf][r][c];
                float v1 = As[buf][r + 8][c];
                float v2 = As[buf][r][c + 4];
                float v3 = As[buf][r + 8][c + 4];
                float h0 = tf32_rna(v0), h1 = tf32_rna(v1),
                      h2 = tf32_rna(v2), h3 = tf32_rna(v3);
                ah[mt][0] = __float_as_uint(h0); al[mt][0] = __float_as_uint(tf32_rna(v0 - h0));
                ah[mt][1] = __float_as_uint(h1); al[mt][1] = __float_as_uint(tf32_rna(v1 - h1));
                ah[mt][2] = __float_as_uint(h2); al[mt][2] = __float_as_uint(tf32_rna(v2 - h2));
                ah[mt][3] = __float_as_uint(h3); al[mt][3] = __float_as_uint(tf32_rna(v3 - h3));
            }
            uint32_t bh[4][2], bl[4][2];
            #pragma unroll
            for (int nt = 0; nt < 4; nt++) {
                int n = wn + nt * 8 + (lane >> 2);
                int k = kk + (lane & 3);
                float v0 = Bs[buf][k][n];
                float v1 = Bs[buf][k + 4][n];
                float h0 = tf32_rna(v0), h1 = tf32_rna(v1);
                bh[nt][0] = __float_as_uint(h0); bl[nt][0] = __float_as_uint(tf32_rna(v0 - h0));
                bh[nt][1] = __float_as_uint(h1); bl[nt][1] = __float_as_uint(tf32_rna(v1 - h1));
            }
            #pragma unroll
            for (int mt = 0; mt < 4; mt++)
                #pragma unroll
                for (int nt = 0; nt < 4; nt++) {
                    mma_tf32(acc[mt][nt], ah[mt], bh[nt]);
                    mma_tf32(acc[mt][nt], al[mt], bh[nt]);
                    mma_tf32(acc[mt][nt], ah[mt], bl[nt]);
                }
        }

        if (ch < 15) storeChunk(buf ^ 1);
        __syncthreads();
    }

    #pragma unroll
    for (int mt = 0; mt < 4; mt++) {
        #pragma unroll
        for (int half = 0; half < 2; half++) {
            int r = blockM + wm + mt * 16 + (lane >> 2) + half * 8;
            if (r < NN) {
                float di = g_dinv[r];
                #pragma unroll
                for (int nt = 0; nt < 4; nt++) {
                    int c = wn + nt * 8 + 2 * (lane & 3);
                    float2 v = make_float2(acc[mt][nt][half * 2 + 0] * di,
                                           acc[mt][nt][half * 2 + 1] * di);
                    *(float2*)&g_h[(size_t)r * HID + c] = v;
                }
            }
        }
    }
}

// ---------------- fused aggregate-1 + GEMM2 -----------------------------------
// 16 nodes / 256-thread block. Warp w gathers+sums rows for nodes nb+2w, nb+2w+1
// (CSR neighbors of g_h, self-loop = own row), then dense z' = (relu(sum*di+b1)@W2)*di.
__global__ __launch_bounds__(256) void k_gemm2(const float* __restrict__ b1,
                                               const float* __restrict__ W2) {
    __shared__ float sRow[16][132];
    __shared__ float sW[HID * NC];
    __shared__ float sB1[HID];
    __shared__ float sDi[16];
    const int tid = threadIdx.x;
    const int warp = tid >> 5, lane = tid & 31;
    const int nb = blockIdx.x * 16;

    for (int i = tid; i < HID * NC; i += 256) sW[i] = W2[i];
    if (tid < HID) sB1[tid] = b1[tid];
    if (tid < 16) { int node = nb + tid; sDi[tid] = (node < NN) ? g_dinv[node] : 0.f; }

    #pragma unroll
    for (int u = 0; u < 2; u++) {
        int ln = 2 * warp + u;
        int node = nb + ln;
        if (node < NN) {
            float4 acc  = *(const float4*)&g_h[(size_t)node * HID + lane * 4]; // self
            float4 acc2 = make_float4(0.f, 0.f, 0.f, 0.f);
            int j   = __ldg(&g_rowptr[node]);
            int end = __ldg(&g_rowptr[node + 1]);
            for (; j + 1 < end; j += 2) {
                int s0 = __ldg(&g_adj[j]);
                int s1 = __ldg(&g_adj[j + 1]);
                float4 v0 = *(const float4*)&g_h[(size_t)s0 * HID + lane * 4];
                float4 v1 = *(const float4*)&g_h[(size_t)s1 * HID + lane * 4];
                acc.x  += v0.x; acc.y  += v0.y; acc.z  += v0.z; acc.w  += v0.w;
                acc2.x += v1.x; acc2.y += v1.y; acc2.z += v1.z; acc2.w += v1.w;
            }
            if (j < end) {
                int s0 = __ldg(&g_adj[j]);
                float4 v0 = *(const float4*)&g_h[(size_t)s0 * HID + lane * 4];
                acc.x += v0.x; acc.y += v0.y; acc.z += v0.z; acc.w += v0.w;
            }
            acc.x += acc2.x; acc.y += acc2.y; acc.z += acc2.z; acc.w += acc2.w;
            *(float4*)&sRow[ln][lane * 4] = acc;
        }
    }
    __syncthreads();

    int ln = tid >> 4, c = tid & 15;
    int node = nb + ln;
    if (node >= NN) return;
    float di = sDi[ln];
    float acc = 0.f;
    #pragma unroll
    for (int k = 0; k < HID; k++) {
        float a = fmaf(sRow[ln][k], di, sB1[k]);
        a = fmaxf(a, 0.f);
        acc = fmaf(a, sW[k * NC + c], acc);
    }
    g_z[(size_t)node * NC + c] = acc * di;
}

// ---------------- aggregate layer 2 (CSR) + final bias ------------------------
// 16 threads per node; thread owns one class column.
__global__ __launch_bounds__(256) void k_agg2(const float* __restrict__ b2,
                                              float* __restrict__ out) {
    int gid = blockIdx.x * blockDim.x + threadIdx.x;
    int node = gid >> 4;
    if (node >= NN) return;
    int c = gid & 15;

    float acc  = g_z[(size_t)node * NC + c];   // self
    float acc2 = 0.f;
    int j   = __ldg(&g_rowptr[node]);
    int end = __ldg(&g_rowptr[node + 1]);
    for (; j + 1 < end; j += 2) {
        int s0 = __ldg(&g_adj[j]);
        int s1 = __ldg(&g_adj[j + 1]);
        acc  += g_z[(size_t)s0 * NC + c];
        acc2 += g_z[(size_t)s1 * NC + c];
    }
    if (j < end) {
        int s0 = __ldg(&g_adj[j]);
        acc += g_z[(size_t)s0 * NC + c];
    }
    acc += acc2;
    out[(size_t)node * NC + c] = fmaf(acc, g_dinv[node], b2[c]);
}

// ---------------- launch -----------------------------------------------------
extern "C" void kernel_launch(void* const* d_in, const int* in_sizes, int n_in,
                              void* d_out, int out_size) {
    const float* x  = (const float*)d_in[0];
    const int*   ei = (const int*)d_in[1];
    const float* W1 = (const float*)d_in[2];
    const float* b1 = (const float*)d_in[3];
    const float* W2 = (const float*)d_in[4];
    const float* b2 = (const float*)d_in[5];
    float* out = (float*)d_out;

    const int* src = ei;        // edge_index[0]
    const int* dst = ei + EE;   // edge_index[1]

    k_deg_init<<<(NN + 255) / 256, 256>>>();
    k_deg_count<<<(EE + 255) / 256, 256>>>(dst);
    k_dinv<<<(NN + 255) / 256, 256>>>();

    // CSR build
    k_scan_block<<<NB_SCAN, 256>>>();
    k_scan_top<<<1, 1>>>();
    k_scan_add<<<(NN + 255) / 256, 256>>>();
    k_fill<<<(EE + 255) / 256, 256>>>(src, dst);

    k_gemm1<<<(NN + 127) / 128, 256>>>(x, W1);        // h' = (x@W1)*dinv

    k_gemm2<<<(NN + 15) / 16, 256>>>(b1, W2);         // gather + dense -> z'

    k_agg2<<<(NN * 16 + 255) / 256, 256>>>(b2, out);  // gather + bias -> out
}

// round 6
// speedup vs baseline: 1.8481x; 1.2284x over previous
#include <cuda_runtime.h>
#include <cuda_bf16.h>
#include <cstdint>

#define NN   100000
#define EE   1600000
#define FIN  256
#define HID  128
#define NC   16
#define NB_SCAN ((NN + 1023) / 1024)

// ---------------- scratch ----------------------------------------------------
static __device__ float g_h[(size_t)NN * HID];     // h' = (x@W1) * dinv[row]
static __device__ float g_z[(size_t)NN * NC];      // z' = (relu(...)@W2)*dinv
static __device__ float g_dinv[NN];
static __device__ int   g_deg[NN];
static __device__ int   g_rowptr[NN + 1];
static __device__ int   g_cursor[NN];
static __device__ int   g_adj[EE];                 // src ids grouped by dst
static __device__ int   g_bsum[NB_SCAN];

// ---------------- degree / normalization ------------------------------------
__global__ void k_deg_init() {
    int i = blockIdx.x * blockDim.x + threadIdx.x;
    if (i < NN) g_deg[i] = 1;   // self loop
}
__global__ void k_deg_count(const int* __restrict__ dst) {
    int e = blockIdx.x * blockDim.x + threadIdx.x;
    if (e < EE) atomicAdd(&g_deg[dst[e]], 1);
}
__global__ void k_dinv() {
    int i = blockIdx.x * blockDim.x + threadIdx.x;
    if (i < NN) g_dinv[i] = rsqrtf((float)g_deg[i]);
}

// ---------------- CSR build ----------------------------------------------------
__global__ __launch_bounds__(256) void k_scan_block() {
    __shared__ int sS[256];
    const int t = threadIdx.x;
    const int base = blockIdx.x * 1024 + t * 4;
    int v[4], s = 0;
    #pragma unroll
    for (int q = 0; q < 4; q++) {
        int i = base + q;
        v[q] = (i < NN) ? (g_deg[i] - 1) : 0;
        s += v[q];
    }
    sS[t] = s;
    __syncthreads();
    #pragma unroll
    for (int off = 1; off < 256; off <<= 1) {
        int x = (t >= off) ? sS[t - off] : 0;
        __syncthreads();
        sS[t] += x;
        __syncthreads();
    }
    if (t == 255) g_bsum[blockIdx.x] = sS[255];
    int run = sS[t] - s;
    #pragma unroll
    for (int q = 0; q < 4; q++) {
        int i = base + q;
        if (i < NN) g_rowptr[i] = run;
        run += v[q];
    }
}
__global__ void k_scan_top() {
    int run = 0;
    for (int b = 0; b < NB_SCAN; b++) { int t = g_bsum[b]; g_bsum[b] = run; run += t; }
}
__global__ void k_scan_add() {
    int i = blockIdx.x * blockDim.x + threadIdx.x;
    if (i < NN) {
        int r = g_rowptr[i] + g_bsum[i >> 10];
        g_rowptr[i] = r;
        g_cursor[i] = r;
    }
    if (i == 0) g_rowptr[NN] = EE;
}
__global__ void k_fill(const int* __restrict__ src, const int* __restrict__ dst) {
    int e = blockIdx.x * blockDim.x + threadIdx.x;
    if (e < EE) {
        int d = dst[e];
        int pos = atomicAdd(&g_cursor[d], 1);
        g_adj[pos] = src[e];
    }
}

// ---------------- bf16 split helpers -----------------------------------------
__device__ __forceinline__ uint32_t pack_bf16x2(float k1, float k0) {
    uint32_t r;
    asm("cvt.rn.bf16x2.f32 %0, %1, %2;" : "=r"(r) : "f"(k1), "f"(k0));
    return r;
}
__device__ __forceinline__ float bf_lo(uint32_t u) { return __uint_as_float(u << 16); }
__device__ __forceinline__ float bf_hi(uint32_t u) { return __uint_as_float(u & 0xFFFF0000u); }

__device__ __forceinline__ void mma_bf16(float* d, const uint32_t* a, const uint32_t* b) {
    asm volatile(
        "mma.sync.aligned.m16n8k16.row.col.f32.bf16.bf16.f32 "
        "{%0,%1,%2,%3}, {%4,%5,%6,%7}, {%8,%9}, {%0,%1,%2,%3};"
        : "+f"(d[0]), "+f"(d[1]), "+f"(d[2]), "+f"(d[3])
        : "r"(a[0]), "r"(a[1]), "r"(a[2]), "r"(a[3]), "r"(b[0]), "r"(b[1]));
}

// ---------------- GEMM1: g_h = (x[N,256] @ W1[256,128]) * dinv ---------------
// 128x128 tile, BK=32, 8 warps (2Mx4N, warp tile 64x32). 3xBF16 split
// (ah*bh + al*bh + ah*bl), split ONCE at staging. Smem: packed bf16x2
// [row][kpair] with pad 20 -> conflict-free fragment loads. Single buffer +
// register prefetch of next chunk.
#define PAD 20
__global__ __launch_bounds__(256, 2) void k_gemm1(const float* __restrict__ A,
                                                  const float* __restrict__ B) {
    __shared__ uint32_t As_h[128][PAD];
    __shared__ uint32_t As_l[128][PAD];
    __shared__ uint32_t Bs_h[128][PAD];
    __shared__ uint32_t Bs_l[128][PAD];

    const int tid  = threadIdx.x;
    const int warp = tid >> 5, lane = tid & 31;
    const int blockM = blockIdx.x * 128;
    const int wm = (warp >> 2) * 64;   // 0 / 64
    const int wn = (warp & 3) * 32;    // 0..96
    const int fr  = lane >> 2;
    const int fkp = lane & 3;

    float acc[4][4][4];
    #pragma unroll
    for (int i = 0; i < 4; i++)
        #pragma unroll
        for (int j = 0; j < 4; j++)
            #pragma unroll
            for (int q = 0; q < 4; q++) acc[i][j][q] = 0.f;

    // staging assignment
    const int aR = tid >> 1;             // A row 0..127
    const int aH = tid & 1;              // k half: 0 -> k 0..15, 1 -> k 16..31
    const int bC = tid & 127;            // B col 0..127
    const int bH = tid >> 7;             // k half

    float4 av[4];     // A: 16 floats (k aH*16 .. +15)
    float  bv[16];    // B: 16 floats (k bH*16 .. +15) for column bC

    auto loadRegs = [&](int k0) {
        const float* arow = &A[(size_t)(blockM + aR) * FIN + k0 + aH * 16];
        bool ok = (blockM + aR) < NN;
        #pragma unroll
        for (int q = 0; q < 4; q++)
            av[q] = ok ? *(const float4*)&arow[q * 4] : make_float4(0.f,0.f,0.f,0.f);
        #pragma unroll
        for (int q = 0; q < 16; q++)
            bv[q] = B[(size_t)(k0 + bH * 16 + q) * HID + bC];
    };
    auto packStore = [&]() {
        // A: 8 kpairs -> As_[aR][aH*8 + j]
        uint32_t h[8], l[8];
        float af[16] = {av[0].x,av[0].y,av[0].z,av[0].w, av[1].x,av[1].y,av[1].z,av[1].w,
                        av[2].x,av[2].y,av[2].z,av[2].w, av[3].x,av[3].y,av[3].z,av[3].w};
        #pragma unroll
        for (int j = 0; j < 8; j++) {
            h[j] = pack_bf16x2(af[2*j+1], af[2*j]);
            l[j] = pack_bf16x2(af[2*j+1] - bf_hi(h[j]), af[2*j] - bf_lo(h[j]));
        }
        *(uint4*)&As_h[aR][aH * 8]     = make_uint4(h[0],h[1],h[2],h[3]);
        *(uint4*)&As_h[aR][aH * 8 + 4] = make_uint4(h[4],h[5],h[6],h[7]);
        *(uint4*)&As_l[aR][aH * 8]     = make_uint4(l[0],l[1],l[2],l[3]);
        *(uint4*)&As_l[aR][aH * 8 + 4] = make_uint4(l[4],l[5],l[6],l[7]);
        // B: 8 kpairs -> Bs_[bC][bH*8 + j]
        #pragma unroll
        for (int j = 0; j < 8; j++) {
            h[j] = pack_bf16x2(bv[2*j+1], bv[2*j]);
            l[j] = pack_bf16x2(bv[2*j+1] - bf_hi(h[j]), bv[2*j] - bf_lo(h[j]));
        }
        *(uint4*)&Bs_h[bC][bH * 8]     = make_uint4(h[0],h[1],h[2],h[3]);
        *(uint4*)&Bs_h[bC][bH * 8 + 4] = make_uint4(h[4],h[5],h[6],h[7]);
        *(uint4*)&Bs_l[bC][bH * 8]     = make_uint4(l[0],l[1],l[2],l[3]);
        *(uint4*)&Bs_l[bC][bH * 8 + 4] = make_uint4(l[4],l[5],l[6],l[7]);
    };

    loadRegs(0);
    for (int ch = 0; ch < 8; ch++) {
        packStore();
        __syncthreads();
        if (ch < 7) loadRegs((ch + 1) * 32);

        #pragma unroll
        for (int kb = 0; kb < 16; kb += 8) {
            uint32_t ah[4][4], bh[4][2];
            #pragma unroll
            for (int mt = 0; mt < 4; mt++) {
                int r = wm + mt * 16 + fr;
                ah[mt][0] = As_h[r][kb + fkp];
                ah[mt][1] = As_h[r + 8][kb + fkp];
                ah[mt][2] = As_h[r][kb + fkp + 4];
                ah[mt][3] = As_h[r + 8][kb + fkp + 4];
            }
            #pragma unroll
            for (int nt = 0; nt < 4; nt++) {
                int c = wn + nt * 8 + fr;
                bh[nt][0] = Bs_h[c][kb + fkp];
                bh[nt][1] = Bs_h[c][kb + fkp + 4];
            }
            #pragma unroll
            for (int mt = 0; mt < 4; mt++)
                #pragma unroll
                for (int nt = 0; nt < 4; nt++)
                    mma_bf16(acc[mt][nt], ah[mt], bh[nt]);
            {   // al * bh
                uint32_t al[4][4];
                #pragma unroll
                for (int mt = 0; mt < 4; mt++) {
                    int r = wm + mt * 16 + fr;
                    al[mt][0] = As_l[r][kb + fkp];
                    al[mt][1] = As_l[r + 8][kb + fkp];
                    al[mt][2] = As_l[r][kb + fkp + 4];
                    al[mt][3] = As_l[r + 8][kb + fkp + 4];
                }
                #pragma unroll
                for (int mt = 0; mt < 4; mt++)
                    #pragma unroll
                    for (int nt = 0; nt < 4; nt++)
                        mma_bf16(acc[mt][nt], al[mt], bh[nt]);
            }
            {   // ah * bl
                uint32_t bl[4][2];
                #pragma unroll
                for (int nt = 0; nt < 4; nt++) {
                    int c = wn + nt * 8 + fr;
                    bl[nt][0] = Bs_l[c][kb + fkp];
                    bl[nt][1] = Bs_l[c][kb + fkp + 4];
                }
                #pragma unroll
                for (int mt = 0; mt < 4; mt++)
                    #pragma unroll
                    for (int nt = 0; nt < 4; nt++)
                        mma_bf16(acc[mt][nt], ah[mt], bl[nt]);
            }
        }
        __syncthreads();
    }

    // epilogue: scale by dinv[row], write h'
    #pragma unroll
    for (int mt = 0; mt < 4; mt++) {
        #pragma unroll
        for (int half = 0; half < 2; half++) {
            int r = blockM + wm + mt * 16 + fr + half * 8;
            if (r < NN) {
                float di = g_dinv[r];
                #pragma unroll
                for (int nt = 0; nt < 4; nt++) {
                    int c = wn + nt * 8 + 2 * fkp;
                    float2 v = make_float2(acc[mt][nt][half * 2 + 0] * di,
                                           acc[mt][nt][half * 2 + 1] * di);
                    *(float2*)&g_h[(size_t)r * HID + c] = v;
                }
            }
        }
    }
}

// ---------------- fused aggregate-1 + GEMM2 -----------------------------------
__global__ __launch_bounds__(256) void k_gemm2(const float* __restrict__ b1,
                                               const float* __restrict__ W2) {
    __shared__ float sRow[16][132];
    __shared__ float sW[HID * NC];
    __shared__ float sB1[HID];
    __shared__ float sDi[16];
    const int tid = threadIdx.x;
    const int warp = tid >> 5, lane = tid & 31;
    const int nb = blockIdx.x * 16;

    for (int i = tid; i < HID * NC; i += 256) sW[i] = W2[i];
    if (tid < HID) sB1[tid] = b1[tid];
    if (tid < 16) { int node = nb + tid; sDi[tid] = (node < NN) ? g_dinv[node] : 0.f; }

    #pragma unroll
    for (int u = 0; u < 2; u++) {
        int ln = 2 * warp + u;
        int node = nb + ln;
        if (node < NN) {
            float4 acc  = *(const float4*)&g_h[(size_t)node * HID + lane * 4]; // self
            float4 acc2 = make_float4(0.f, 0.f, 0.f, 0.f);
            int j   = __ldg(&g_rowptr[node]);
            int end = __ldg(&g_rowptr[node + 1]);
            for (; j + 1 < end; j += 2) {
                int s0 = __ldg(&g_adj[j]);
                int s1 = __ldg(&g_adj[j + 1]);
                float4 v0 = *(const float4*)&g_h[(size_t)s0 * HID + lane * 4];
                float4 v1 = *(const float4*)&g_h[(size_t)s1 * HID + lane * 4];
                acc.x  += v0.x; acc.y  += v0.y; acc.z  += v0.z; acc.w  += v0.w;
                acc2.x += v1.x; acc2.y += v1.y; acc2.z += v1.z; acc2.w += v1.w;
            }
            if (j < end) {
                int s0 = __ldg(&g_adj[j]);
                float4 v0 = *(const float4*)&g_h[(size_t)s0 * HID + lane * 4];
                acc.x += v0.x; acc.y += v0.y; acc.z += v0.z; acc.w += v0.w;
            }
            acc.x += acc2.x; acc.y += acc2.y; acc.z += acc2.z; acc.w += acc2.w;
            *(float4*)&sRow[ln][lane * 4] = acc;
        }
    }
    __syncthreads();

    int ln = tid >> 4, c = tid & 15;
    int node = nb + ln;
    if (node >= NN) return;
    float di = sDi[ln];
    float acc = 0.f;
    #pragma unroll
    for (int k = 0; k < HID; k++) {
        float a = fmaf(sRow[ln][k], di, sB1[k]);
        a = fmaxf(a, 0.f);
        acc = fmaf(a, sW[k * NC + c], acc);
    }
    g_z[(size_t)node * NC + c] = acc * di;
}

// ---------------- aggregate layer 2 (CSR) + final bias ------------------------
__global__ __launch_bounds__(256) void k_agg2(const float* __restrict__ b2,
                                              float* __restrict__ out) {
    int gid = blockIdx.x * blockDim.x + threadIdx.x;
    int node = gid >> 4;
    if (node >= NN) return;
    int c = gid & 15;

    float acc  = g_z[(size_t)node * NC + c];   // self
    float acc2 = 0.f;
    int j   = __ldg(&g_rowptr[node]);
    int end = __ldg(&g_rowptr[node + 1]);
    for (; j + 1 < end; j += 2) {
        int s0 = __ldg(&g_adj[j]);
        int s1 = __ldg(&g_adj[j + 1]);
        acc  += g_z[(size_t)s0 * NC + c];
        acc2 += g_z[(size_t)s1 * NC + c];
    }
    if (j < end) {
        int s0 = __ldg(&g_adj[j]);
        acc += g_z[(size_t)s0 * NC + c];
    }
    acc += acc2;
    out[(size_t)node * NC + c] = fmaf(acc, g_dinv[node], b2[c]);
}

// ---------------- launch -----------------------------------------------------
extern "C" void kernel_launch(void* const* d_in, const int* in_sizes, int n_in,
                              void* d_out, int out_size) {
    const float* x  = (const float*)d_in[0];
    const int*   ei = (const int*)d_in[1];
    const float* W1 = (const float*)d_in[2];
    const float* b1 = (const float*)d_in[3];
    const float* W2 = (const float*)d_in[4];
    const float* b2 = (const float*)d_in[5];
    float* out = (float*)d_out;

    const int* src = ei;        // edge_index[0]
    const int* dst = ei + EE;   // edge_index[1]

    k_deg_init<<<(NN + 255) / 256, 256>>>();
    k_deg_count<<<(EE + 255) / 256, 256>>>(dst);
    k_dinv<<<(NN + 255) / 256, 256>>>();

    // CSR build
    k_scan_block<<<NB_SCAN, 256>>>();
    k_scan_top<<<1, 1>>>();
    k_scan_add<<<(NN + 255) / 256, 256>>>();
    k_fill<<<(EE + 255) / 256, 256>>>(src, dst);

    k_gemm1<<<(NN + 127) / 128, 256>>>(x, W1);        // h' = (x@W1)*dinv

    k_gemm2<<<(NN + 15) / 16, 256>>>(b1, W2);         // gather + dense -> z'

    k_agg2<<<(NN * 16 + 255) / 256, 256>>>(b2, out);  // gather + bias -> out
}